// round 15
// baseline (speedup 1.0000x reference)
#include <cuda_runtime.h>
#include <cuda_fp16.h>
#include <cstdint>
#include <math.h>

#define NL 6
#define NH 6
#define NE 384
#define HS 64
#define NT 256
#define NB 64
#define NV 65
#define MTOT (NB*NT)      /* 16384 rows */
#define FF (4*NE)         /* 1536 */
#define NQKV (3*NE)       /* 1152 */
#define LNEPS 1e-5f
#define NLOSSB (MTOT/8)   /* 2048 loss blocks */

// ================= scratch =================
__device__ __align__(256) float g_x[MTOT*NE];
__device__ __align__(256) __half g_h16[MTOT*NE];
__device__ __align__(256) __half g_qkv16[3*MTOT*NE];
__device__ __align__(256) __half g_o16[MTOT*NE];
__device__ __align__(256) __half g_m16[MTOT*FF];
__device__ __align__(256) float g_logits[MTOT*NV];
__device__ double g_losspart[NLOSSB];
__device__ __align__(256) __half g_wqkv[NL*NQKV*NE];
__device__ __align__(256) __half g_wpr[NL*NE*NE];
__device__ __align__(256) __half g_w1[NL*FF*NE];
__device__ __align__(256) __half g_w2[NL*NE*FF];

// ================= PTX helpers (base ISA: sm_80+) =================
__device__ __forceinline__ uint32_t smem_u32(const void* p) {
    uint32_t a;
    asm("{ .reg .u64 t; cvta.to.shared.u64 t, %1; cvt.u32.u64 %0, t; }" : "=r"(a) : "l"(p));
    return a;
}
__device__ __forceinline__ void cp16(uint32_t dst, const void* src) {
    asm volatile("cp.async.cg.shared.global [%0], [%1], 16;" :: "r"(dst), "l"(src));
}
#define CP_COMMIT() asm volatile("cp.async.commit_group;" ::: "memory")
#define CP_WAIT1()  asm volatile("cp.async.wait_group 1;" ::: "memory")
#define CP_WAIT0()  asm volatile("cp.async.wait_group 0;" ::: "memory")
__device__ __forceinline__ void ldm_x4(uint32_t& r0, uint32_t& r1, uint32_t& r2, uint32_t& r3, uint32_t addr) {
    asm volatile("ldmatrix.sync.aligned.m8n8.x4.shared.b16 {%0,%1,%2,%3}, [%4];"
        : "=r"(r0), "=r"(r1), "=r"(r2), "=r"(r3) : "r"(addr));
}
__device__ __forceinline__ void ldm_x4_t(uint32_t& r0, uint32_t& r1, uint32_t& r2, uint32_t& r3, uint32_t addr) {
    asm volatile("ldmatrix.sync.aligned.m8n8.x4.trans.shared.b16 {%0,%1,%2,%3}, [%4];"
        : "=r"(r0), "=r"(r1), "=r"(r2), "=r"(r3) : "r"(addr));
}
__device__ __forceinline__ void mma_f16(float* c, uint32_t a0, uint32_t a1, uint32_t a2, uint32_t a3,
                                        uint32_t b0, uint32_t b1) {
    asm volatile("mma.sync.aligned.m16n8k16.row.col.f32.f16.f16.f32 "
        "{%0,%1,%2,%3}, {%4,%5,%6,%7}, {%8,%9}, {%0,%1,%2,%3};"
        : "+f"(c[0]), "+f"(c[1]), "+f"(c[2]), "+f"(c[3])
        : "r"(a0), "r"(a1), "r"(a2), "r"(a3), "r"(b0), "r"(b1));
}
__device__ __forceinline__ void mma_f16acc(uint32_t& c0, uint32_t& c1,
                                           uint32_t a0, uint32_t a1, uint32_t a2, uint32_t a3,
                                           uint32_t b0, uint32_t b1) {
    asm volatile("mma.sync.aligned.m16n8k16.row.col.f16.f16.f16.f16 "
        "{%0,%1}, {%2,%3,%4,%5}, {%6,%7}, {%0,%1};"
        : "+r"(c0), "+r"(c1)
        : "r"(a0), "r"(a1), "r"(a2), "r"(a3), "r"(b0), "r"(b1));
}
__device__ __forceinline__ float lo2f(uint32_t u) { __half2 h = *reinterpret_cast<__half2*>(&u); return __low2float(h); }
__device__ __forceinline__ float hi2f(uint32_t u) { __half2 h = *reinterpret_cast<__half2*>(&u); return __high2float(h); }
__device__ __forceinline__ uint32_t pack2(float x, float y) {
    __half2 h2 = __floats2half2_rn(x, y);
    return *reinterpret_cast<uint32_t*>(&h2);
}

// ============ merged weight prep (single fp16, transposed [N,K]) ============
#define PREP_N0 ((long)NL*NQKV*NE)
#define PREP_N1 (PREP_N0 + (long)NL*NE*NE)
#define PREP_N2 (PREP_N1 + (long)NL*NE*FF)
#define PREP_N3 (PREP_N2 + (long)NL*FF*NE)

__global__ void prep_all_kernel(const float* __restrict__ Wq, const float* __restrict__ Wk,
                                const float* __restrict__ Wv, const float* __restrict__ Wpr,
                                const float* __restrict__ W1, const float* __restrict__ W2,
                                __half* __restrict__ wq, __half* __restrict__ wp,
                                __half* __restrict__ w1, __half* __restrict__ w2) {
    long i = (long)blockIdx.x * 256 + threadIdx.x;
    if (i < PREP_N0) {
        int e = (int)(i % NE); int n = (int)((i / NE) % NQKV); int l = (int)(i / ((long)NE * NQKV));
        int which = n / NE, rem = n % NE, h = rem >> 6, s = rem & 63;
        const float* W = (which == 0) ? Wq : (which == 1) ? Wk : Wv;
        wq[i] = __float2half_rn(W[(((size_t)l * NH + h) * NE + e) * HS + s]);
    } else if (i < PREP_N1) {
        long j = i - PREP_N0;
        int k = (int)(j % NE); int n = (int)((j / NE) % NE); int l = (int)(j / ((long)NE * NE));
        wp[j] = __float2half_rn(Wpr[((size_t)l * NE + k) * NE + n]);
    } else if (i < PREP_N2) {
        long j = i - PREP_N1;
        int k = (int)(j % NE); int n = (int)((j / NE) % FF); int l = (int)(j / ((long)NE * FF));
        w1[j] = __float2half_rn(W1[((size_t)l * NE + k) * FF + n]);
    } else if (i < PREP_N3) {
        long j = i - PREP_N2;
        int k = (int)(j % FF); int n = (int)((j / FF) % NE); int l = (int)(j / ((long)FF * NE));
        w2[j] = __float2half_rn(W2[((size_t)l * FF + k) * NE + n]);
    }
}

// ================= embedding =================
__global__ void embed_kernel(const int* __restrict__ idx, const float* __restrict__ tok,
                             const float* __restrict__ pos) {
    int i = blockIdx.x * blockDim.x + threadIdx.x;
    if (i >= MTOT * NE) return;
    int r = i / NE, e = i - r * NE;
    int t = r & (NT - 1);
    g_x[i] = tok[idx[r] * NE + e] + pos[t * NE + e];
}

// ========== LN -> fp16 (batched; 128 rows per 512-thread block) ==========
__global__ void __launch_bounds__(512, 2)
ln16_kernel(const float* __restrict__ x, const float* __restrict__ gw,
            const float* __restrict__ bw, __half* __restrict__ oh) {
    const int lane = threadIdx.x & 31, wid = threadIdx.x >> 5;
    const int m0 = blockIdx.x * 128;
    const float4* gw4 = (const float4*)gw;
    const float4* bw4 = (const float4*)bw;
    float4 gg[3], bb[3];
    #pragma unroll
    for (int j = 0; j < 3; j++) { gg[j] = gw4[lane + 32 * j]; bb[j] = bw4[lane + 32 * j]; }
    #pragma unroll
    for (int it = 0; it < 4; it++) {
        int r0 = wid * 8 + it * 2;
        const float4* p0 = (const float4*)(x + (size_t)(m0 + r0) * NE);
        const float4* p1 = (const float4*)(x + (size_t)(m0 + r0 + 1) * NE);
        float4 a[3], b[3];
        #pragma unroll
        for (int j = 0; j < 3; j++) { a[j] = p0[lane + 32 * j]; b[j] = p1[lane + 32 * j]; }
        float s0 = 0.f, q0 = 0.f, s1 = 0.f, q1 = 0.f;
        #pragma unroll
        for (int j = 0; j < 3; j++) {
            s0 += a[j].x + a[j].y + a[j].z + a[j].w;
            q0 += a[j].x * a[j].x + a[j].y * a[j].y + a[j].z * a[j].z + a[j].w * a[j].w;
            s1 += b[j].x + b[j].y + b[j].z + b[j].w;
            q1 += b[j].x * b[j].x + b[j].y * b[j].y + b[j].z * b[j].z + b[j].w * b[j].w;
        }
        #pragma unroll
        for (int o = 16; o; o >>= 1) {
            s0 += __shfl_xor_sync(0xffffffffu, s0, o);
            q0 += __shfl_xor_sync(0xffffffffu, q0, o);
            s1 += __shfl_xor_sync(0xffffffffu, s1, o);
            q1 += __shfl_xor_sync(0xffffffffu, q1, o);
        }
        float mean0 = s0 * (1.0f / NE), mean1 = s1 * (1.0f / NE);
        float inv0 = rsqrtf(q0 * (1.0f / NE) - mean0 * mean0 + LNEPS);
        float inv1 = rsqrtf(q1 * (1.0f / NE) - mean1 * mean1 + LNEPS);
        __half* o0 = oh + (size_t)(m0 + r0) * NE;
        __half* o1 = oh + (size_t)(m0 + r0 + 1) * NE;
        #pragma unroll
        for (int j = 0; j < 3; j++) {
            int c = (lane + 32 * j) * 4;
            uint2 w0, w1;
            w0.x = pack2((a[j].x - mean0) * inv0 * gg[j].x + bb[j].x,
                         (a[j].y - mean0) * inv0 * gg[j].y + bb[j].y);
            w0.y = pack2((a[j].z - mean0) * inv0 * gg[j].z + bb[j].z,
                         (a[j].w - mean0) * inv0 * gg[j].w + bb[j].w);
            w1.x = pack2((b[j].x - mean1) * inv1 * gg[j].x + bb[j].x,
                         (b[j].y - mean1) * inv1 * gg[j].y + bb[j].y);
            w1.y = pack2((b[j].z - mean1) * inv1 * gg[j].z + bb[j].z,
                         (b[j].w - mean1) * inv1 * gg[j].w + bb[j].w);
            *(uint2*)(o0 + c) = w0;
            *(uint2*)(o1 + c) = w1;
        }
    }
}

// ======= HMMA GEMM: 128x128 tile, BK=64 chunks, 3-stage ring, occ 2 =======
// TYPE 0: QKV scatter fp16; TYPE 1: out = res + acc + bias (fp32); TYPE 2: relu fp16
#define GPITCH 72                    /* halves per smem row (144B) */
#define TILE_B (128*GPITCH*2)        /* 18432 */
#define STAGE_B (2*TILE_B)           /* A B = 36864 */
#define HM_SMEM (3*STAGE_B)          /* 110592; x2 CTAs = 221184 <= 228KB */

template<int TYPE>
__global__ void __launch_bounds__(512, 2)
gemm_main(const __half* __restrict__ A, const __half* __restrict__ Bh,
          const float* __restrict__ bias, const float* __restrict__ res,
          float* __restrict__ out0, __half* __restrict__ oh, int K) {
    extern __shared__ __align__(128) char smem[];
    const uint32_t sbase = smem_u32(smem);
    const int tid = threadIdx.x;
    const int lane = tid & 31, wid = tid >> 5;
    const int warp_m = wid >> 2, warp_n = wid & 3;
    const int m0 = blockIdx.x * 128, n0 = blockIdx.y * 128;

    const int nc = K / 64;

    // loader: 2048 16B-positions per chunk (2 tiles x 128 rows x 8 col-chunks)
    const int li_r  = tid >> 2;            // base row for it-loop stride pattern
    // we derive per-iteration indices inside issue

    #define GM_ISSUE(chunk, stg_) do {                                         \
        uint32_t _sb = sbase + (uint32_t)(stg_) * STAGE_B;                     \
        int _k0 = (chunk) * 64;                                                \
        _Pragma("unroll")                                                      \
        for (int _it = 0; _it < 4; _it++) {                                    \
            int _i = tid + _it * 512;                                          \
            int _r = _i >> 4, _cp = _i & 15;                                   \
            int _tile = _cp >> 3, _ch = _cp & 7;                               \
            uint32_t _dst = _sb + (uint32_t)_tile * TILE_B +                   \
                            (uint32_t)(_r * 144 + _ch * 16);                   \
            const __half* _src = _tile == 0                                    \
                ? (A  + (size_t)(m0 + _r) * K + _k0 + _ch * 8)                 \
                : (Bh + (size_t)(n0 + _r) * K + _k0 + _ch * 8);                \
            cp16(_dst, _src);                                                  \
        }                                                                      \
    } while (0)

    GM_ISSUE(0, 0); CP_COMMIT();
    if (nc > 1) { GM_ISSUE(1, 1); }
    CP_COMMIT();

    float acc[2][4][4];
    #pragma unroll
    for (int i = 0; i < 2; i++)
        #pragma unroll
        for (int j = 0; j < 4; j++)
            acc[i][j][0] = acc[i][j][1] = acc[i][j][2] = acc[i][j][3] = 0.f;

    const int a_row = warp_m * 32 + (lane & 15);
    const int a_colsel = (lane >> 4) * 8;
    const int b_row = warp_n * 32 + (lane & 7) + ((lane >> 4) << 3);
    const int b_colsel = ((lane >> 3) & 1) * 8;

    int stg = 0;
    for (int c = 0; c < nc; c++) {
        CP_WAIT1();
        __syncthreads();        // single barrier: also protects reuse of stage consumed at c-1
        uint32_t stage = sbase + (uint32_t)stg * STAGE_B;
        if (c + 2 < nc) GM_ISSUE(c + 2, (stg + 2) % 3);
        CP_COMMIT();
        #pragma unroll
        for (int k16 = 0; k16 < 64; k16 += 16) {
            uint32_t af[2][4], bh4[2][4];
            #pragma unroll
            for (int mf2 = 0; mf2 < 2; mf2++) {
                uint32_t addr = stage + ((uint32_t)(a_row + mf2 * 16) * GPITCH + k16 + a_colsel) * 2;
                ldm_x4(af[mf2][0], af[mf2][1], af[mf2][2], af[mf2][3], addr);
            }
            #pragma unroll
            for (int np = 0; np < 2; np++) {
                uint32_t addr = stage + ((uint32_t)(b_row + np * 16) * GPITCH + k16 + b_colsel) * 2;
                ldm_x4(bh4[np][0], bh4[np][1], bh4[np][2], bh4[np][3], addr + 1 * TILE_B);
            }
            #pragma unroll
            for (int mf = 0; mf < 2; mf++)
                #pragma unroll
                for (int np = 0; np < 2; np++)
                    #pragma unroll
                    for (int sub = 0; sub < 2; sub++)
                        mma_f16(acc[mf][np * 2 + sub], af[mf][0], af[mf][1], af[mf][2], af[mf][3],
                                bh4[np][sub * 2], bh4[np][sub * 2 + 1]);
        }
        stg = (stg == 2) ? 0 : stg + 1;
    }
    #undef GM_ISSUE
    (void)li_r;

    #pragma unroll
    for (int mf = 0; mf < 2; mf++) {
        #pragma unroll
        for (int nf = 0; nf < 4; nf++) {
            #pragma unroll
            for (int hp = 0; hp < 2; hp++) {
                int r = m0 + warp_m * 32 + mf * 16 + (lane >> 2) + hp * 8;
                int n = n0 + warp_n * 32 + nf * 8 + ((lane & 3) << 1);
                float v0 = acc[mf][nf][hp * 2 + 0];
                float v1 = acc[mf][nf][hp * 2 + 1];
                if (TYPE == 0) {
                    int bb = r >> 8, t = r & (NT - 1);
                    int which = n / NE, rem = n - which * NE;
                    int hh = rem >> 6, s = rem & 63;
                    size_t o = (size_t)which * ((size_t)MTOT * NE) +
                               ((((size_t)bb * NH + hh) * NT + t) * HS + s);
                    *(uint32_t*)&oh[o] = pack2(v0, v1);
                } else if (TYPE == 1) {
                    size_t o = (size_t)r * NE + n;
                    float2 rv = *(const float2*)&res[o];
                    float2 ov;
                    ov.x = rv.x + v0 + bias[n];
                    ov.y = rv.y + v1 + bias[n + 1];
                    *(float2*)&out0[o] = ov;
                } else {
                    float y0 = fmaxf(v0 + bias[n], 0.f);
                    float y1 = fmaxf(v1 + bias[n + 1], 0.f);
                    *(uint32_t*)&oh[(size_t)r * FF + n] = pack2(y0, y1);
                }
            }
        }
    }
}

// ===== flash attention: 3-stage K/V ring, single barrier/iter, heavy tiles first =====
#define AQT 128
#define AKT 64
#define APITCH 72
#define ATILE_B (AKT*APITCH*2)      /* 9216 */
#define ASTAGE_B (2*ATILE_B)        /* K,V = 18432 */
#define AQ_OFF (3*ASTAGE_B)         /* 55296 */
#define AT_SMEM (AQ_OFF + 128*APITCH*2)  /* 73728 */

__device__ __forceinline__ void flash_issue(uint32_t bs, int kt, int tid,
    const __half* Kp, const __half* Vp) {
    #pragma unroll
    for (int i2 = 0; i2 < 2; i2++) {
        int i = tid + i2 * 256;
        int r = i >> 3, ch = i & 7;
        uint32_t off = (uint32_t)(r * (APITCH * 2) + ch * 16);
        size_t g = (size_t)(kt * AKT + r) * HS + ch * 8;
        cp16(bs + 0 * ATILE_B + off, Kp + g);
        cp16(bs + 1 * ATILE_B + off, Vp + g);
    }
}

__global__ void __launch_bounds__(256, 2)
flash_kernel(const __half* __restrict__ qkv, __half* __restrict__ oo) {
    extern __shared__ __align__(128) char smem[];
    const uint32_t sbase = smem_u32(smem);
    const int tid = threadIdx.x, lane = tid & 31, wid = tid >> 5;
    const int bh = blockIdx.x;
    const int qt = 1 - blockIdx.y;          // heavy tiles (qt=1) scheduled first
    const int b = bh / NH, h = bh - b * NH;
    const size_t TS = (size_t)MTOT * NE;
    const size_t base_bh = (size_t)bh * NT * HS;
    const __half* Qp = qkv + base_bh;
    const __half* Kp = qkv + TS + base_bh;
    const __half* Vp = qkv + 2 * TS + base_bh;
    const int nkt = 2 * (qt + 1);

    for (int i = tid; i < 1024; i += 256) {
        int r = i >> 3, ch = i & 7;
        uint32_t off = (uint32_t)(r * (APITCH * 2) + ch * 16);
        cp16(sbase + AQ_OFF + off, Qp + (size_t)(qt * AQT + r) * HS + ch * 8);
    }
    flash_issue(sbase, 0, tid, Kp, Vp);
    CP_COMMIT();
    if (1 < nkt) flash_issue(sbase + ASTAGE_B, 1, tid, Kp, Vp);
    CP_COMMIT();
    CP_WAIT1();
    __syncthreads();
    uint32_t qf[4][4];
    {
        int a_row = wid * 16 + (lane & 15);
        int a_col = (lane >> 4) * 8;
        #pragma unroll
        for (int ks = 0; ks < 4; ks++) {
            uint32_t ad = sbase + AQ_OFF + (uint32_t)((a_row * APITCH + ks * 16 + a_col) * 2);
            ldm_x4(qf[ks][0], qf[ks][1], qf[ks][2], qf[ks][3], ad);
        }
    }

    float of[8][4];
    #pragma unroll
    for (int i = 0; i < 8; i++)
        #pragma unroll
        for (int j = 0; j < 4; j++) of[i][j] = 0.f;
    float m0 = -1e30f, m1 = -1e30f, l0 = 0.f, l1 = 0.f;
    const float scale = rsqrtf((float)NE);
    const int qrow0 = qt * AQT + wid * 16 + (lane >> 2);
    const int warp_qmax = qt * AQT + wid * 16 + 15;

    int stg = 0;
    for (int kt = 0; kt < nkt; kt++) {
        CP_WAIT1();
        __syncthreads();
        uint32_t kb = sbase + stg * ASTAGE_B;
        if (kt + 2 < nkt)
            flash_issue(sbase + ((stg + 2) % 3) * ASTAGE_B, kt + 2, tid, Kp, Vp);
        CP_COMMIT();
        if (kt * AKT <= warp_qmax) {
            uint32_t sc16[8][2];
            #pragma unroll
            for (int i = 0; i < 8; i++) { sc16[i][0] = 0u; sc16[i][1] = 0u; }
            #pragma unroll
            for (int ks = 0; ks < 4; ks++) {
                uint32_t bf[4][4];
                #pragma unroll
                for (int np = 0; np < 4; np++) {
                    int brow = np * 16 + (lane & 7) + ((lane >> 4) << 3);
                    int bcol = ks * 16 + ((lane >> 3) & 1) * 8;
                    uint32_t ad = kb + (uint32_t)((brow * APITCH + bcol) * 2);
                    ldm_x4(bf[np][0], bf[np][1], bf[np][2], bf[np][3], ad);
                }
                #pragma unroll
                for (int np = 0; np < 4; np++)
                    #pragma unroll
                    for (int sub = 0; sub < 2; sub++)
                        mma_f16acc(sc16[np * 2 + sub][0], sc16[np * 2 + sub][1],
                                   qf[ks][0], qf[ks][1], qf[ks][2], qf[ks][3],
                                   bf[np][sub * 2], bf[np][sub * 2 + 1]);
            }
            float sc[8][4];
            #pragma unroll
            for (int nf = 0; nf < 8; nf++) {
                sc[nf][0] = lo2f(sc16[nf][0]); sc[nf][1] = hi2f(sc16[nf][0]);
                sc[nf][2] = lo2f(sc16[nf][1]); sc[nf][3] = hi2f(sc16[nf][1]);
            }
            #pragma unroll
            for (int nf = 0; nf < 8; nf++)
                #pragma unroll
                for (int j = 0; j < 4; j++) {
                    int kcol = kt * AKT + nf * 8 + ((lane & 3) << 1) + (j & 1);
                    int qr = (j < 2) ? qrow0 : (qrow0 + 8);
                    sc[nf][j] = (kcol <= qr) ? sc[nf][j] * scale : -1e30f;
                }
            float ml0 = -1e30f, ml1 = -1e30f;
            #pragma unroll
            for (int nf = 0; nf < 8; nf++) {
                ml0 = fmaxf(ml0, fmaxf(sc[nf][0], sc[nf][1]));
                ml1 = fmaxf(ml1, fmaxf(sc[nf][2], sc[nf][3]));
            }
            ml0 = fmaxf(ml0, __shfl_xor_sync(0xffffffffu, ml0, 1));
            ml0 = fmaxf(ml0, __shfl_xor_sync(0xffffffffu, ml0, 2));
            ml1 = fmaxf(ml1, __shfl_xor_sync(0xffffffffu, ml1, 1));
            ml1 = fmaxf(ml1, __shfl_xor_sync(0xffffffffu, ml1, 2));
            float mn0 = fmaxf(m0, ml0), mn1 = fmaxf(m1, ml1);
            float a0 = __expf(m0 - mn0), a1 = __expf(m1 - mn1);
            float rs0 = 0.f, rs1 = 0.f;
            #pragma unroll
            for (int nf = 0; nf < 8; nf++) {
                sc[nf][0] = __expf(sc[nf][0] - mn0); rs0 += sc[nf][0];
                sc[nf][1] = __expf(sc[nf][1] - mn0); rs0 += sc[nf][1];
                sc[nf][2] = __expf(sc[nf][2] - mn1); rs1 += sc[nf][2];
                sc[nf][3] = __expf(sc[nf][3] - mn1); rs1 += sc[nf][3];
            }
            rs0 += __shfl_xor_sync(0xffffffffu, rs0, 1);
            rs0 += __shfl_xor_sync(0xffffffffu, rs0, 2);
            rs1 += __shfl_xor_sync(0xffffffffu, rs1, 1);
            rs1 += __shfl_xor_sync(0xffffffffu, rs1, 2);
            #pragma unroll
            for (int nf = 0; nf < 8; nf++) {
                of[nf][0] *= a0; of[nf][1] *= a0;
                of[nf][2] *= a1; of[nf][3] *= a1;
            }
            l0 = l0 * a0 + rs0; l1 = l1 * a1 + rs1;
            m0 = mn0; m1 = mn1;
            #pragma unroll
            for (int ks = 0; ks < 4; ks++) {
                uint32_t pf[4];
                pf[0] = pack2(sc[2 * ks][0], sc[2 * ks][1]);
                pf[1] = pack2(sc[2 * ks][2], sc[2 * ks][3]);
                pf[2] = pack2(sc[2 * ks + 1][0], sc[2 * ks + 1][1]);
                pf[3] = pack2(sc[2 * ks + 1][2], sc[2 * ks + 1][3]);
                uint32_t vf[4][4];
                #pragma unroll
                for (int nd = 0; nd < 4; nd++) {
                    int vrow = ks * 16 + (lane & 7) + (((lane >> 3) & 1) << 3);
                    int vcol = nd * 16 + ((lane >> 4) << 3);
                    uint32_t ad = kb + (uint32_t)((vrow * APITCH + vcol) * 2);
                    ldm_x4_t(vf[nd][0], vf[nd][1], vf[nd][2], vf[nd][3], ad + ATILE_B);
                }
                #pragma unroll
                for (int nd = 0; nd < 4; nd++)
                    #pragma unroll
                    for (int sub = 0; sub < 2; sub++)
                        mma_f16(of[nd * 2 + sub], pf[0], pf[1], pf[2], pf[3],
                                vf[nd][sub * 2], vf[nd][sub * 2 + 1]);
            }
        }
        stg = (stg == 2) ? 0 : stg + 1;
    }

    float inv0 = 1.f / l0, inv1 = 1.f / l1;
    size_t row0 = ((size_t)b * NT + qrow0) * NE + h * HS;
    size_t row1 = row0 + (size_t)8 * NE;
    #pragma unroll
    for (int nf = 0; nf < 8; nf++) {
        int d = nf * 8 + ((lane & 3) << 1);
        *reinterpret_cast<uint32_t*>(&oo[row0 + d]) = pack2(of[nf][0] * inv0, of[nf][1] * inv0);
        *reinterpret_cast<uint32_t*>(&oo[row1 + d]) = pack2(of[nf][2] * inv1, of[nf][3] * inv1);
    }
}

// ========== LM head with fused final LN: logits = LN(x) @ Wlm + blm ==========
__global__ void gemm_lm_kernel(const float* __restrict__ x,
                               const float* __restrict__ gw, const float* __restrict__ bw,
                               const float* __restrict__ Bm, const float* __restrict__ bias,
                               float* __restrict__ C) {
    __shared__ float As[16][64];
    __shared__ float Bs[16][68];
    __shared__ float stats[64][2];
    __shared__ float gwb[NE], bwb[NE];
    int tid = threadIdx.x;
    int lane = tid & 31, wrp = tid >> 5;
    int rowBase = blockIdx.x * 64, colBase = blockIdx.y * 64;
    for (int i = tid; i < NE; i += 256) { gwb[i] = gw[i]; bwb[i] = bw[i]; }
    #pragma unroll
    for (int it = 0; it < 8; it++) {
        int r = wrp * 8 + it;
        const float* xr = x + (size_t)(rowBase + r) * NE;
        float s = 0.f, q = 0.f;
        #pragma unroll
        for (int j = 0; j < 12; j++) { float v = xr[lane + 32 * j]; s += v; q += v * v; }
        #pragma unroll
        for (int o = 16; o; o >>= 1) {
            s += __shfl_xor_sync(0xffffffffu, s, o);
            q += __shfl_xor_sync(0xffffffffu, q, o);
        }
        if (lane == 0) {
            float mean = s * (1.0f / NE);
            stats[r][0] = mean;
            stats[r][1] = rsqrtf(q * (1.0f / NE) - mean * mean + LNEPS);
        }
    }
    __syncthreads();
    int tx = tid & 15, ty = tid >> 4;
    float acc[4][4] = {};
    int la_m = tid >> 2, la_k = (tid & 3) * 4;
    int lb_k = tid >> 4, lb_n = (tid & 15) * 4;
    float mean = stats[la_m][0], inv = stats[la_m][1];
    for (int k0 = 0; k0 < NE; k0 += 16) {
        float4 a4 = *(const float4*)(x + (size_t)(rowBase + la_m) * NE + k0 + la_k);
        As[la_k + 0][la_m] = (a4.x - mean) * inv * gwb[k0 + la_k + 0] + bwb[k0 + la_k + 0];
        As[la_k + 1][la_m] = (a4.y - mean) * inv * gwb[k0 + la_k + 1] + bwb[k0 + la_k + 1];
        As[la_k + 2][la_m] = (a4.z - mean) * inv * gwb[k0 + la_k + 2] + bwb[k0 + la_k + 2];
        As[la_k + 3][la_m] = (a4.w - mean) * inv * gwb[k0 + la_k + 3] + bwb[k0 + la_k + 3];
        #pragma unroll
        for (int u = 0; u < 4; u++) {
            int n = colBase + lb_n + u;
            Bs[lb_k][lb_n + u] = (n < NV) ? Bm[(size_t)(k0 + lb_k) * NV + n] : 0.f;
        }
        __syncthreads();
        #pragma unroll
        for (int kk = 0; kk < 16; kk++) {
            float4 a = *(float4*)&As[kk][ty * 4];
            float4 b = *(float4*)&Bs[kk][tx * 4];
            float av[4] = {a.x, a.y, a.z, a.w};
            float bv[4] = {b.x, b.y, b.z, b.w};
            #pragma unroll
            for (int i = 0; i < 4; i++)
                #pragma unroll
                for (int j = 0; j < 4; j++)
                    acc[i][j] += av[i] * bv[j];
        }
        __syncthreads();
    }
    #pragma unroll
    for (int i = 0; i < 4; i++) {
        int r = rowBase + ty * 4 + i;
        #pragma unroll
        for (int j = 0; j < 4; j++) {
            int c = colBase + tx * 4 + j;
            if (c >= NV) continue;
            C[(size_t)r * NV + c] = acc[i][j] + bias[c];
        }
    }
}

// ================= loss (per-block partials, no atomics) =================
__global__ void loss_kernel(const float* __restrict__ logits, const int* __restrict__ tgt) {
    int row = blockIdx.x * 8 + (threadIdx.x >> 5);
    int lane = threadIdx.x & 31;
    int wrp = threadIdx.x >> 5;
    const float* lp = logits + (size_t)row * NV;
    float v0 = lp[lane];
    float v1 = (lane + 32 < NV) ? lp[lane + 32] : -1e30f;
    float v2 = (lane + 64 < NV) ? lp[lane + 64] : -1e30f;
    float m = fmaxf(v0, fmaxf(v1, v2));
    #pragma unroll
    for (int off = 16; off; off >>= 1) m = fmaxf(m, __shfl_xor_sync(0xffffffffu, m, off));
    float su = expf(v0 - m);
    if (lane + 32 < NV) su += expf(v1 - m);
    if (lane + 64 < NV) su += expf(v2 - m);
    #pragma unroll
    for (int off = 16; off; off >>= 1) su += __shfl_xor_sync(0xffffffffu, su, off);
    __shared__ double sm[8];
    if (lane == 0) {
        float lt = lp[tgt[row]];
        sm[wrp] = -((double)lt - (double)m - (double)logf(su));
    }
    __syncthreads();
    if (threadIdx.x == 0) {
        double t = sm[0] + sm[1] + sm[2] + sm[3] + sm[4] + sm[5] + sm[6] + sm[7];
        g_losspart[blockIdx.x] = t;
    }
}

__global__ void finalize_loss_kernel(float* __restrict__ out) {
    int tid = threadIdx.x;
    double s = 0.0;
    for (int i = tid; i < NLOSSB; i += 256) s += g_losspart[i];
    #pragma unroll
    for (int off = 16; off; off >>= 1) s += __shfl_xor_sync(0xffffffffu, s, off);
    __shared__ double sm[8];
    if ((tid & 31) == 0) sm[tid >> 5] = s;
    __syncthreads();
    if (tid == 0) {
        double t = sm[0] + sm[1] + sm[2] + sm[3] + sm[4] + sm[5] + sm[6] + sm[7];
        out[0] = (float)(t / (double)MTOT);
    }
}

// ================= launch =================
extern "C" void kernel_launch(void* const* d_in, const int* in_sizes, int n_in,
                              void* d_out, int out_size) {
    const int*   idx  = (const int*)d_in[0];
    const int*   tgt  = (const int*)d_in[1];
    const float* tok  = (const float*)d_in[2];
    const float* pos  = (const float*)d_in[3];
    const float* Wq   = (const float*)d_in[4];
    const float* Wk   = (const float*)d_in[5];
    const float* Wv   = (const float*)d_in[6];
    const float* Wpr  = (const float*)d_in[7];
    const float* bpr  = (const float*)d_in[8];
    const float* ln1g = (const float*)d_in[9];
    const float* ln1b = (const float*)d_in[10];
    const float* ln2g = (const float*)d_in[11];
    const float* ln2b = (const float*)d_in[12];
    const float* W1   = (const float*)d_in[13];
    const float* b1   = (const float*)d_in[14];
    const float* W2   = (const float*)d_in[15];
    const float* b2   = (const float*)d_in[16];
    const float* lnfg = (const float*)d_in[17];
    const float* lnfb = (const float*)d_in[18];
    const float* Wlm  = (const float*)d_in[19];
    const float* blm  = (const float*)d_in[20];
    float* out = (float*)d_out;

    float *px, *plog;
    __half *ph16, *pqkv, *po16, *pm16;
    __half *wq, *wp, *w1, *w2;
    cudaGetSymbolAddress((void**)&px, g_x);
    cudaGetSymbolAddress((void**)&plog, g_logits);
    cudaGetSymbolAddress((void**)&ph16, g_h16);
    cudaGetSymbolAddress((void**)&pqkv, g_qkv16);
    cudaGetSymbolAddress((void**)&po16, g_o16);
    cudaGetSymbolAddress((void**)&pm16, g_m16);
    cudaGetSymbolAddress((void**)&wq, g_wqkv);
    cudaGetSymbolAddress((void**)&wp, g_wpr);
    cudaGetSymbolAddress((void**)&w1, g_w1);
    cudaGetSymbolAddress((void**)&w2, g_w2);

    cudaFuncSetAttribute(flash_kernel, cudaFuncAttributeMaxDynamicSharedMemorySize, AT_SMEM);
    cudaFuncSetAttribute(gemm_main<0>, cudaFuncAttributeMaxDynamicSharedMemorySize, HM_SMEM);
    cudaFuncSetAttribute(gemm_main<1>, cudaFuncAttributeMaxDynamicSharedMemorySize, HM_SMEM);
    cudaFuncSetAttribute(gemm_main<2>, cudaFuncAttributeMaxDynamicSharedMemorySize, HM_SMEM);

    prep_all_kernel<<<(int)((PREP_N3 + 255) / 256), 256>>>(Wq, Wk, Wv, Wpr, W1, W2,
                                                           wq, wp, w1, w2);

    embed_kernel<<<(MTOT * NE + 255) / 256, 256>>>(idx, tok, pos);

    for (int l = 0; l < NL; l++) {
        ln16_kernel<<<MTOT / 128, 512>>>(px, ln1g + l * NE, ln1b + l * NE, ph16);
        gemm_main<0><<<dim3(MTOT / 128, NQKV / 128), 512, HM_SMEM>>>(
            ph16, wq + (size_t)l * NQKV * NE, nullptr, nullptr, nullptr, pqkv, NE);
        flash_kernel<<<dim3(NB * NH, 2), 256, AT_SMEM>>>(pqkv, po16);
        gemm_main<1><<<dim3(MTOT / 128, NE / 128), 512, HM_SMEM>>>(
            po16, wp + (size_t)l * NE * NE, bpr + l * NE, px, px, nullptr, NE);
        ln16_kernel<<<MTOT / 128, 512>>>(px, ln2g + l * NE, ln2b + l * NE, ph16);
        gemm_main<2><<<dim3(MTOT / 128, FF / 128), 512, HM_SMEM>>>(
            ph16, w1 + (size_t)l * FF * NE, b1 + l * FF, nullptr, nullptr, pm16, NE);
        gemm_main<1><<<dim3(MTOT / 128, NE / 128), 512, HM_SMEM>>>(
            pm16, w2 + (size_t)l * NE * FF, b2 + l * NE, px, px, nullptr, FF);
    }

    const int NLOG = MTOT * NV;
    float* logits = (out_size >= NLOG) ? out : plog;
    gemm_lm_kernel<<<dim3(MTOT / 64, (NV + 63) / 64), 256>>>(px, lnfg, lnfb, Wlm, blm, logits);

    loss_kernel<<<NLOSSB, 256>>>(logits, tgt);
    if (out_size > NLOG)       finalize_loss_kernel<<<1, 256>>>(out + NLOG);
    else if (out_size >= 1 && out_size < NLOG) finalize_loss_kernel<<<1, 256>>>(out);
}

// round 16
// speedup vs baseline: 1.0465x; 1.0465x over previous
#include <cuda_runtime.h>
#include <cuda_fp16.h>
#include <cstdint>
#include <math.h>

#define NL 6
#define NH 6
#define NE 384
#define HS 64
#define NT 256
#define NB 64
#define NV 65
#define MTOT (NB*NT)      /* 16384 rows */
#define FF (4*NE)         /* 1536 */
#define NQKV (3*NE)       /* 1152 */
#define LNEPS 1e-5f
#define NLOSSB (MTOT/8)   /* 2048 loss blocks */

// ================= scratch =================
__device__ __align__(256) float g_x[MTOT*NE];
__device__ __align__(256) __half g_h16[MTOT*NE];
__device__ __align__(256) __half g_qkv16[3*MTOT*NE];
__device__ __align__(256) __half g_o16[MTOT*NE];
__device__ __align__(256) __half g_m16[MTOT*FF];
__device__ __align__(256) float g_logits[MTOT*NV];
__device__ double g_losspart[NLOSSB];
__device__ __align__(256) __half g_wqkv[NL*NQKV*NE];
__device__ __align__(256) __half g_wpr[NL*NE*NE];
__device__ __align__(256) __half g_w1[NL*FF*NE];
__device__ __align__(256) __half g_w2[NL*NE*FF];

// ================= PTX helpers (base ISA: sm_80+) =================
__device__ __forceinline__ uint32_t smem_u32(const void* p) {
    uint32_t a;
    asm("{ .reg .u64 t; cvta.to.shared.u64 t, %1; cvt.u32.u64 %0, t; }" : "=r"(a) : "l"(p));
    return a;
}
__device__ __forceinline__ void cp16(uint32_t dst, const void* src) {
    asm volatile("cp.async.cg.shared.global [%0], [%1], 16;" :: "r"(dst), "l"(src));
}
#define CP_COMMIT() asm volatile("cp.async.commit_group;" ::: "memory")
#define CP_WAIT2()  asm volatile("cp.async.wait_group 2;" ::: "memory")
#define CP_WAIT1()  asm volatile("cp.async.wait_group 1;" ::: "memory")
#define CP_WAIT0()  asm volatile("cp.async.wait_group 0;" ::: "memory")
__device__ __forceinline__ void ldm_x4(uint32_t& r0, uint32_t& r1, uint32_t& r2, uint32_t& r3, uint32_t addr) {
    asm volatile("ldmatrix.sync.aligned.m8n8.x4.shared.b16 {%0,%1,%2,%3}, [%4];"
        : "=r"(r0), "=r"(r1), "=r"(r2), "=r"(r3) : "r"(addr));
}
__device__ __forceinline__ void ldm_x4_t(uint32_t& r0, uint32_t& r1, uint32_t& r2, uint32_t& r3, uint32_t addr) {
    asm volatile("ldmatrix.sync.aligned.m8n8.x4.trans.shared.b16 {%0,%1,%2,%3}, [%4];"
        : "=r"(r0), "=r"(r1), "=r"(r2), "=r"(r3) : "r"(addr));
}
__device__ __forceinline__ void mma_f16(float* c, uint32_t a0, uint32_t a1, uint32_t a2, uint32_t a3,
                                        uint32_t b0, uint32_t b1) {
    asm volatile("mma.sync.aligned.m16n8k16.row.col.f32.f16.f16.f32 "
        "{%0,%1,%2,%3}, {%4,%5,%6,%7}, {%8,%9}, {%0,%1,%2,%3};"
        : "+f"(c[0]), "+f"(c[1]), "+f"(c[2]), "+f"(c[3])
        : "r"(a0), "r"(a1), "r"(a2), "r"(a3), "r"(b0), "r"(b1));
}
__device__ __forceinline__ void mma_f16acc(uint32_t& c0, uint32_t& c1,
                                           uint32_t a0, uint32_t a1, uint32_t a2, uint32_t a3,
                                           uint32_t b0, uint32_t b1) {
    asm volatile("mma.sync.aligned.m16n8k16.row.col.f16.f16.f16.f16 "
        "{%0,%1}, {%2,%3,%4,%5}, {%6,%7}, {%0,%1};"
        : "+r"(c0), "+r"(c1)
        : "r"(a0), "r"(a1), "r"(a2), "r"(a3), "r"(b0), "r"(b1));
}
__device__ __forceinline__ float lo2f(uint32_t u) { __half2 h = *reinterpret_cast<__half2*>(&u); return __low2float(h); }
__device__ __forceinline__ float hi2f(uint32_t u) { __half2 h = *reinterpret_cast<__half2*>(&u); return __high2float(h); }
__device__ __forceinline__ uint32_t pack2(float x, float y) {
    __half2 h2 = __floats2half2_rn(x, y);
    return *reinterpret_cast<uint32_t*>(&h2);
}

// ============ merged weight prep (single fp16, transposed [N,K]) ============
#define PREP_N0 ((long)NL*NQKV*NE)
#define PREP_N1 (PREP_N0 + (long)NL*NE*NE)
#define PREP_N2 (PREP_N1 + (long)NL*NE*FF)
#define PREP_N3 (PREP_N2 + (long)NL*FF*NE)

__global__ void prep_all_kernel(const float* __restrict__ Wq, const float* __restrict__ Wk,
                                const float* __restrict__ Wv, const float* __restrict__ Wpr,
                                const float* __restrict__ W1, const float* __restrict__ W2,
                                __half* __restrict__ wq, __half* __restrict__ wp,
                                __half* __restrict__ w1, __half* __restrict__ w2) {
    long i = (long)blockIdx.x * 256 + threadIdx.x;
    if (i < PREP_N0) {
        int e = (int)(i % NE); int n = (int)((i / NE) % NQKV); int l = (int)(i / ((long)NE * NQKV));
        int which = n / NE, rem = n % NE, h = rem >> 6, s = rem & 63;
        const float* W = (which == 0) ? Wq : (which == 1) ? Wk : Wv;
        wq[i] = __float2half_rn(W[(((size_t)l * NH + h) * NE + e) * HS + s]);
    } else if (i < PREP_N1) {
        long j = i - PREP_N0;
        int k = (int)(j % NE); int n = (int)((j / NE) % NE); int l = (int)(j / ((long)NE * NE));
        wp[j] = __float2half_rn(Wpr[((size_t)l * NE + k) * NE + n]);
    } else if (i < PREP_N2) {
        long j = i - PREP_N1;
        int k = (int)(j % NE); int n = (int)((j / NE) % FF); int l = (int)(j / ((long)NE * FF));
        w1[j] = __float2half_rn(W1[((size_t)l * NE + k) * FF + n]);
    } else if (i < PREP_N3) {
        long j = i - PREP_N2;
        int k = (int)(j % FF); int n = (int)((j / FF) % NE); int l = (int)(j / ((long)FF * NE));
        w2[j] = __float2half_rn(W2[((size_t)l * FF + k) * NE + n]);
    }
}

// ================= embedding =================
__global__ void embed_kernel(const int* __restrict__ idx, const float* __restrict__ tok,
                             const float* __restrict__ pos) {
    int i = blockIdx.x * blockDim.x + threadIdx.x;
    if (i >= MTOT * NE) return;
    int r = i / NE, e = i - r * NE;
    int t = r & (NT - 1);
    g_x[i] = tok[idx[r] * NE + e] + pos[t * NE + e];
}

// ========== LN -> fp16 (batched; 128 rows per 512-thread block) ==========
__global__ void __launch_bounds__(512, 2)
ln16_kernel(const float* __restrict__ x, const float* __restrict__ gw,
            const float* __restrict__ bw, __half* __restrict__ oh) {
    const int lane = threadIdx.x & 31, wid = threadIdx.x >> 5;
    const int m0 = blockIdx.x * 128;
    const float4* gw4 = (const float4*)gw;
    const float4* bw4 = (const float4*)bw;
    float4 gg[3], bb[3];
    #pragma unroll
    for (int j = 0; j < 3; j++) { gg[j] = gw4[lane + 32 * j]; bb[j] = bw4[lane + 32 * j]; }
    #pragma unroll
    for (int it = 0; it < 4; it++) {
        int r0 = wid * 8 + it * 2;
        const float4* p0 = (const float4*)(x + (size_t)(m0 + r0) * NE);
        const float4* p1 = (const float4*)(x + (size_t)(m0 + r0 + 1) * NE);
        float4 a[3], b[3];
        #pragma unroll
        for (int j = 0; j < 3; j++) { a[j] = p0[lane + 32 * j]; b[j] = p1[lane + 32 * j]; }
        float s0 = 0.f, q0 = 0.f, s1 = 0.f, q1 = 0.f;
        #pragma unroll
        for (int j = 0; j < 3; j++) {
            s0 += a[j].x + a[j].y + a[j].z + a[j].w;
            q0 += a[j].x * a[j].x + a[j].y * a[j].y + a[j].z * a[j].z + a[j].w * a[j].w;
            s1 += b[j].x + b[j].y + b[j].z + b[j].w;
            q1 += b[j].x * b[j].x + b[j].y * b[j].y + b[j].z * b[j].z + b[j].w * b[j].w;
        }
        #pragma unroll
        for (int o = 16; o; o >>= 1) {
            s0 += __shfl_xor_sync(0xffffffffu, s0, o);
            q0 += __shfl_xor_sync(0xffffffffu, q0, o);
            s1 += __shfl_xor_sync(0xffffffffu, s1, o);
            q1 += __shfl_xor_sync(0xffffffffu, q1, o);
        }
        float mean0 = s0 * (1.0f / NE), mean1 = s1 * (1.0f / NE);
        float inv0 = rsqrtf(q0 * (1.0f / NE) - mean0 * mean0 + LNEPS);
        float inv1 = rsqrtf(q1 * (1.0f / NE) - mean1 * mean1 + LNEPS);
        __half* o0 = oh + (size_t)(m0 + r0) * NE;
        __half* o1 = oh + (size_t)(m0 + r0 + 1) * NE;
        #pragma unroll
        for (int j = 0; j < 3; j++) {
            int c = (lane + 32 * j) * 4;
            uint2 w0, w1;
            w0.x = pack2((a[j].x - mean0) * inv0 * gg[j].x + bb[j].x,
                         (a[j].y - mean0) * inv0 * gg[j].y + bb[j].y);
            w0.y = pack2((a[j].z - mean0) * inv0 * gg[j].z + bb[j].z,
                         (a[j].w - mean0) * inv0 * gg[j].w + bb[j].w);
            w1.x = pack2((b[j].x - mean1) * inv1 * gg[j].x + bb[j].x,
                         (b[j].y - mean1) * inv1 * gg[j].y + bb[j].y);
            w1.y = pack2((b[j].z - mean1) * inv1 * gg[j].z + bb[j].z,
                         (b[j].w - mean1) * inv1 * gg[j].w + bb[j].w);
            *(uint2*)(o0 + c) = w0;
            *(uint2*)(o1 + c) = w1;
        }
    }
}

// ======= HMMA GEMM (R14 proven): 128x128 tile, BK=32, 4-stage ring, occ 2 =======
// K is a compile-time template parameter (KV): full unroll + folded addressing.
// TYPE 0: QKV scatter fp16; TYPE 1: out = res + acc + bias (fp32); TYPE 2: relu fp16
#define PITCH 40
#define TILE_B (128*PITCH*2)        /* 10240 */
#define STAGE_B (2*TILE_B)          /* A B = 20480 */
#define HM_SMEM (4*STAGE_B)         /* 81920 */

template<int TYPE, int KV>
__global__ void __launch_bounds__(512, 2)
gemm_main(const __half* __restrict__ A, const __half* __restrict__ Bh,
          const float* __restrict__ bias, const float* __restrict__ res,
          float* __restrict__ out0, __half* __restrict__ oh) {
    extern __shared__ __align__(128) char smem[];
    const uint32_t sbase = smem_u32(smem);
    const int tid = threadIdx.x;
    const int lane = tid & 31, wid = tid >> 5;
    const int warp_m = wid >> 2, warp_n = wid & 3;
    const int m0 = blockIdx.x * 128, n0 = blockIdx.y * 128;

    const int lrow = tid >> 2, lc = tid & 3;
    const uint32_t ldst = (uint32_t)(lrow * 80 + lc * 16);
    const __half* srcA  = A  + (size_t)(m0 + lrow) * KV + lc * 8;
    const __half* srcBh = Bh + (size_t)(n0 + lrow) * KV + lc * 8;

    constexpr int nc = KV / 32;
    #pragma unroll
    for (int st = 0; st < 3; st++) {
        uint32_t b = sbase + st * STAGE_B + ldst;
        int k0 = st * 32;
        cp16(b + 0 * TILE_B, srcA + k0);
        cp16(b + 1 * TILE_B, srcBh + k0);
        CP_COMMIT();
    }

    float acc[2][4][4];
    #pragma unroll
    for (int i = 0; i < 2; i++)
        #pragma unroll
        for (int j = 0; j < 4; j++)
            acc[i][j][0] = acc[i][j][1] = acc[i][j][2] = acc[i][j][3] = 0.f;

    const int a_row = warp_m * 32 + (lane & 15);
    const int a_colsel = (lane >> 4) * 8;
    const int b_row = warp_n * 32 + (lane & 7) + ((lane >> 4) << 3);
    const int b_colsel = ((lane >> 3) & 1) * 8;

    for (int c = 0; c < nc; c++) {
        CP_WAIT2();
        __syncthreads();        // single barrier: also protects stage (c-1)&3 reuse
        uint32_t stage = sbase + (c & 3) * STAGE_B;
        if (c + 3 < nc) {       // prefetch into stage consumed at iteration c-1
            uint32_t b = sbase + ((c + 3) & 3) * STAGE_B + ldst;
            int k0 = (c + 3) * 32;
            cp16(b + 0 * TILE_B, srcA + k0);
            cp16(b + 1 * TILE_B, srcBh + k0);
        }
        CP_COMMIT();
        #pragma unroll
        for (int k16 = 0; k16 < 32; k16 += 16) {
            uint32_t af[2][4], bh4[2][4];
            #pragma unroll
            for (int mf2 = 0; mf2 < 2; mf2++) {
                uint32_t addr = stage + ((uint32_t)(a_row + mf2 * 16) * PITCH + k16 + a_colsel) * 2;
                ldm_x4(af[mf2][0], af[mf2][1], af[mf2][2], af[mf2][3], addr);
            }
            #pragma unroll
            for (int np = 0; np < 2; np++) {
                uint32_t addr = stage + ((uint32_t)(b_row + np * 16) * PITCH + k16 + b_colsel) * 2;
                ldm_x4(bh4[np][0], bh4[np][1], bh4[np][2], bh4[np][3], addr + 1 * TILE_B);
            }
            #pragma unroll
            for (int mf = 0; mf < 2; mf++)
                #pragma unroll
                for (int np = 0; np < 2; np++)
                    #pragma unroll
                    for (int sub = 0; sub < 2; sub++)
                        mma_f16(acc[mf][np * 2 + sub], af[mf][0], af[mf][1], af[mf][2], af[mf][3],
                                bh4[np][sub * 2], bh4[np][sub * 2 + 1]);
        }
    }

    #pragma unroll
    for (int mf = 0; mf < 2; mf++) {
        #pragma unroll
        for (int nf = 0; nf < 4; nf++) {
            #pragma unroll
            for (int hp = 0; hp < 2; hp++) {
                int r = m0 + warp_m * 32 + mf * 16 + (lane >> 2) + hp * 8;
                int n = n0 + warp_n * 32 + nf * 8 + ((lane & 3) << 1);
                float v0 = acc[mf][nf][hp * 2 + 0];
                float v1 = acc[mf][nf][hp * 2 + 1];
                if (TYPE == 0) {
                    int bb = r >> 8, t = r & (NT - 1);
                    int which = n / NE, rem = n - which * NE;
                    int hh = rem >> 6, s = rem & 63;
                    size_t o = (size_t)which * ((size_t)MTOT * NE) +
                               ((((size_t)bb * NH + hh) * NT + t) * HS + s);
                    *(uint32_t*)&oh[o] = pack2(v0, v1);
                } else if (TYPE == 1) {
                    size_t o = (size_t)r * NE + n;
                    float2 rv = *(const float2*)&res[o];
                    float2 ov;
                    ov.x = rv.x + v0 + bias[n];
                    ov.y = rv.y + v1 + bias[n + 1];
                    *(float2*)&out0[o] = ov;
                } else {
                    float y0 = fmaxf(v0 + bias[n], 0.f);
                    float y1 = fmaxf(v1 + bias[n + 1], 0.f);
                    *(uint32_t*)&oh[(size_t)r * FF + n] = pack2(y0, y1);
                }
            }
        }
    }
}

// ===== flash attention: 3-stage K/V ring, single barrier/iter, heavy tiles first =====
#define AQT 128
#define AKT 64
#define APITCH 72
#define ATILE_B (AKT*APITCH*2)      /* 9216 */
#define ASTAGE_B (2*ATILE_B)        /* K,V = 18432 */
#define AQ_OFF (3*ASTAGE_B)         /* 55296 */
#define AT_SMEM (AQ_OFF + 128*APITCH*2)  /* 73728 */

__device__ __forceinline__ void flash_issue(uint32_t bs, int kt, int tid,
    const __half* Kp, const __half* Vp) {
    #pragma unroll
    for (int i2 = 0; i2 < 2; i2++) {
        int i = tid + i2 * 256;
        int r = i >> 3, ch = i & 7;
        uint32_t off = (uint32_t)(r * (APITCH * 2) + ch * 16);
        size_t g = (size_t)(kt * AKT + r) * HS + ch * 8;
        cp16(bs + 0 * ATILE_B + off, Kp + g);
        cp16(bs + 1 * ATILE_B + off, Vp + g);
    }
}

__global__ void __launch_bounds__(256, 2)
flash_kernel(const __half* __restrict__ qkv, __half* __restrict__ oo) {
    extern __shared__ __align__(128) char smem[];
    const uint32_t sbase = smem_u32(smem);
    const int tid = threadIdx.x, lane = tid & 31, wid = tid >> 5;
    const int bh = blockIdx.x;
    const int qt = 1 - blockIdx.y;          // heavy tiles (qt=1) scheduled first
    const int b = bh / NH, h = bh - b * NH;
    const size_t TS = (size_t)MTOT * NE;
    const size_t base_bh = (size_t)bh * NT * HS;
    const __half* Qp = qkv + base_bh;
    const __half* Kp = qkv + TS + base_bh;
    const __half* Vp = qkv + 2 * TS + base_bh;
    const int nkt = 2 * (qt + 1);

    for (int i = tid; i < 1024; i += 256) {
        int r = i >> 3, ch = i & 7;
        uint32_t off = (uint32_t)(r * (APITCH * 2) + ch * 16);
        cp16(sbase + AQ_OFF + off, Qp + (size_t)(qt * AQT + r) * HS + ch * 8);
    }
    flash_issue(sbase, 0, tid, Kp, Vp);
    CP_COMMIT();
    if (1 < nkt) flash_issue(sbase + ASTAGE_B, 1, tid, Kp, Vp);
    CP_COMMIT();
    CP_WAIT1();
    __syncthreads();
    uint32_t qf[4][4];
    {
        int a_row = wid * 16 + (lane & 15);
        int a_col = (lane >> 4) * 8;
        #pragma unroll
        for (int ks = 0; ks < 4; ks++) {
            uint32_t ad = sbase + AQ_OFF + (uint32_t)((a_row * APITCH + ks * 16 + a_col) * 2);
            ldm_x4(qf[ks][0], qf[ks][1], qf[ks][2], qf[ks][3], ad);
        }
    }

    float of[8][4];
    #pragma unroll
    for (int i = 0; i < 8; i++)
        #pragma unroll
        for (int j = 0; j < 4; j++) of[i][j] = 0.f;
    float m0 = -1e30f, m1 = -1e30f, l0 = 0.f, l1 = 0.f;
    const float scale = rsqrtf((float)NE);
    const int qrow0 = qt * AQT + wid * 16 + (lane >> 2);
    const int warp_qmax = qt * AQT + wid * 16 + 15;

    int stg = 0;
    for (int kt = 0; kt < nkt; kt++) {
        CP_WAIT1();
        __syncthreads();
        uint32_t kb = sbase + stg * ASTAGE_B;
        if (kt + 2 < nkt)
            flash_issue(sbase + ((stg + 2) % 3) * ASTAGE_B, kt + 2, tid, Kp, Vp);
        CP_COMMIT();
        if (kt * AKT <= warp_qmax) {
            uint32_t sc16[8][2];
            #pragma unroll
            for (int i = 0; i < 8; i++) { sc16[i][0] = 0u; sc16[i][1] = 0u; }
            #pragma unroll
            for (int ks = 0; ks < 4; ks++) {
                uint32_t bf[4][4];
                #pragma unroll
                for (int np = 0; np < 4; np++) {
                    int brow = np * 16 + (lane & 7) + ((lane >> 4) << 3);
                    int bcol = ks * 16 + ((lane >> 3) & 1) * 8;
                    uint32_t ad = kb + (uint32_t)((brow * APITCH + bcol) * 2);
                    ldm_x4(bf[np][0], bf[np][1], bf[np][2], bf[np][3], ad);
                }
                #pragma unroll
                for (int np = 0; np < 4; np++)
                    #pragma unroll
                    for (int sub = 0; sub < 2; sub++)
                        mma_f16acc(sc16[np * 2 + sub][0], sc16[np * 2 + sub][1],
                                   qf[ks][0], qf[ks][1], qf[ks][2], qf[ks][3],
                                   bf[np][sub * 2], bf[np][sub * 2 + 1]);
            }
            float sc[8][4];
            #pragma unroll
            for (int nf = 0; nf < 8; nf++) {
                sc[nf][0] = lo2f(sc16[nf][0]); sc[nf][1] = hi2f(sc16[nf][0]);
                sc[nf][2] = lo2f(sc16[nf][1]); sc[nf][3] = hi2f(sc16[nf][1]);
            }
            #pragma unroll
            for (int nf = 0; nf < 8; nf++)
                #pragma unroll
                for (int j = 0; j < 4; j++) {
                    int kcol = kt * AKT + nf * 8 + ((lane & 3) << 1) + (j & 1);
                    int qr = (j < 2) ? qrow0 : (qrow0 + 8);
                    sc[nf][j] = (kcol <= qr) ? sc[nf][j] * scale : -1e30f;
                }
            float ml0 = -1e30f, ml1 = -1e30f;
            #pragma unroll
            for (int nf = 0; nf < 8; nf++) {
                ml0 = fmaxf(ml0, fmaxf(sc[nf][0], sc[nf][1]));
                ml1 = fmaxf(ml1, fmaxf(sc[nf][2], sc[nf][3]));
            }
            ml0 = fmaxf(ml0, __shfl_xor_sync(0xffffffffu, ml0, 1));
            ml0 = fmaxf(ml0, __shfl_xor_sync(0xffffffffu, ml0, 2));
            ml1 = fmaxf(ml1, __shfl_xor_sync(0xffffffffu, ml1, 1));
            ml1 = fmaxf(ml1, __shfl_xor_sync(0xffffffffu, ml1, 2));
            float mn0 = fmaxf(m0, ml0), mn1 = fmaxf(m1, ml1);
            float a0 = __expf(m0 - mn0), a1 = __expf(m1 - mn1);
            float rs0 = 0.f, rs1 = 0.f;
            #pragma unroll
            for (int nf = 0; nf < 8; nf++) {
                sc[nf][0] = __expf(sc[nf][0] - mn0); rs0 += sc[nf][0];
                sc[nf][1] = __expf(sc[nf][1] - mn0); rs0 += sc[nf][1];
                sc[nf][2] = __expf(sc[nf][2] - mn1); rs1 += sc[nf][2];
                sc[nf][3] = __expf(sc[nf][3] - mn1); rs1 += sc[nf][3];
            }
            rs0 += __shfl_xor_sync(0xffffffffu, rs0, 1);
            rs0 += __shfl_xor_sync(0xffffffffu, rs0, 2);
            rs1 += __shfl_xor_sync(0xffffffffu, rs1, 1);
            rs1 += __shfl_xor_sync(0xffffffffu, rs1, 2);
            #pragma unroll
            for (int nf = 0; nf < 8; nf++) {
                of[nf][0] *= a0; of[nf][1] *= a0;
                of[nf][2] *= a1; of[nf][3] *= a1;
            }
            l0 = l0 * a0 + rs0; l1 = l1 * a1 + rs1;
            m0 = mn0; m1 = mn1;
            #pragma unroll
            for (int ks = 0; ks < 4; ks++) {
                uint32_t pf[4];
                pf[0] = pack2(sc[2 * ks][0], sc[2 * ks][1]);
                pf[1] = pack2(sc[2 * ks][2], sc[2 * ks][3]);
                pf[2] = pack2(sc[2 * ks + 1][0], sc[2 * ks + 1][1]);
                pf[3] = pack2(sc[2 * ks + 1][2], sc[2 * ks + 1][3]);
                uint32_t vf[4][4];
                #pragma unroll
                for (int nd = 0; nd < 4; nd++) {
                    int vrow = ks * 16 + (lane & 7) + (((lane >> 3) & 1) << 3);
                    int vcol = nd * 16 + ((lane >> 4) << 3);
                    uint32_t ad = kb + (uint32_t)((vrow * APITCH + vcol) * 2);
                    ldm_x4_t(vf[nd][0], vf[nd][1], vf[nd][2], vf[nd][3], ad + ATILE_B);
                }
                #pragma unroll
                for (int nd = 0; nd < 4; nd++)
                    #pragma unroll
                    for (int sub = 0; sub < 2; sub++)
                        mma_f16(of[nd * 2 + sub], pf[0], pf[1], pf[2], pf[3],
                                vf[nd][sub * 2], vf[nd][sub * 2 + 1]);
            }
        }
        stg = (stg == 2) ? 0 : stg + 1;
    }

    float inv0 = 1.f / l0, inv1 = 1.f / l1;
    size_t row0 = ((size_t)b * NT + qrow0) * NE + h * HS;
    size_t row1 = row0 + (size_t)8 * NE;
    #pragma unroll
    for (int nf = 0; nf < 8; nf++) {
        int d = nf * 8 + ((lane & 3) << 1);
        *reinterpret_cast<uint32_t*>(&oo[row0 + d]) = pack2(of[nf][0] * inv0, of[nf][1] * inv0);
        *reinterpret_cast<uint32_t*>(&oo[row1 + d]) = pack2(of[nf][2] * inv1, of[nf][3] * inv1);
    }
}

// ========== LM head with fused final LN: logits = LN(x) @ Wlm + blm ==========
__global__ void gemm_lm_kernel(const float* __restrict__ x,
                               const float* __restrict__ gw, const float* __restrict__ bw,
                               const float* __restrict__ Bm, const float* __restrict__ bias,
                               float* __restrict__ C) {
    __shared__ float As[16][64];
    __shared__ float Bs[16][68];
    __shared__ float stats[64][2];
    __shared__ float gwb[NE], bwb[NE];
    int tid = threadIdx.x;
    int lane = tid & 31, wrp = tid >> 5;
    int rowBase = blockIdx.x * 64, colBase = blockIdx.y * 64;
    for (int i = tid; i < NE; i += 256) { gwb[i] = gw[i]; bwb[i] = bw[i]; }
    #pragma unroll
    for (int it = 0; it < 8; it++) {
        int r = wrp * 8 + it;
        const float* xr = x + (size_t)(rowBase + r) * NE;
        float s = 0.f, q = 0.f;
        #pragma unroll
        for (int j = 0; j < 12; j++) { float v = xr[lane + 32 * j]; s += v; q += v * v; }
        #pragma unroll
        for (int o = 16; o; o >>= 1) {
            s += __shfl_xor_sync(0xffffffffu, s, o);
            q += __shfl_xor_sync(0xffffffffu, q, o);
        }
        if (lane == 0) {
            float mean = s * (1.0f / NE);
            stats[r][0] = mean;
            stats[r][1] = rsqrtf(q * (1.0f / NE) - mean * mean + LNEPS);
        }
    }
    __syncthreads();
    int tx = tid & 15, ty = tid >> 4;
    float acc[4][4] = {};
    int la_m = tid >> 2, la_k = (tid & 3) * 4;
    int lb_k = tid >> 4, lb_n = (tid & 15) * 4;
    float mean = stats[la_m][0], inv = stats[la_m][1];
    for (int k0 = 0; k0 < NE; k0 += 16) {
        float4 a4 = *(const float4*)(x + (size_t)(rowBase + la_m) * NE + k0 + la_k);
        As[la_k + 0][la_m] = (a4.x - mean) * inv * gwb[k0 + la_k + 0] + bwb[k0 + la_k + 0];
        As[la_k + 1][la_m] = (a4.y - mean) * inv * gwb[k0 + la_k + 1] + bwb[k0 + la_k + 1];
        As[la_k + 2][la_m] = (a4.z - mean) * inv * gwb[k0 + la_k + 2] + bwb[k0 + la_k + 2];
        As[la_k + 3][la_m] = (a4.w - mean) * inv * gwb[k0 + la_k + 3] + bwb[k0 + la_k + 3];
        #pragma unroll
        for (int u = 0; u < 4; u++) {
            int n = colBase + lb_n + u;
            Bs[lb_k][lb_n + u] = (n < NV) ? Bm[(size_t)(k0 + lb_k) * NV + n] : 0.f;
        }
        __syncthreads();
        #pragma unroll
        for (int kk = 0; kk < 16; kk++) {
            float4 a = *(float4*)&As[kk][ty * 4];
            float4 b = *(float4*)&Bs[kk][tx * 4];
            float av[4] = {a.x, a.y, a.z, a.w};
            float bv[4] = {b.x, b.y, b.z, b.w};
            #pragma unroll
            for (int i = 0; i < 4; i++)
                #pragma unroll
                for (int j = 0; j < 4; j++)
                    acc[i][j] += av[i] * bv[j];
        }
        __syncthreads();
    }
    #pragma unroll
    for (int i = 0; i < 4; i++) {
        int r = rowBase + ty * 4 + i;
        #pragma unroll
        for (int j = 0; j < 4; j++) {
            int c = colBase + tx * 4 + j;
            if (c >= NV) continue;
            C[(size_t)r * NV + c] = acc[i][j] + bias[c];
        }
    }
}

// ================= loss (per-block partials, no atomics) =================
__global__ void loss_kernel(const float* __restrict__ logits, const int* __restrict__ tgt) {
    int row = blockIdx.x * 8 + (threadIdx.x >> 5);
    int lane = threadIdx.x & 31;
    int wrp = threadIdx.x >> 5;
    const float* lp = logits + (size_t)row * NV;
    float v0 = lp[lane];
    float v1 = (lane + 32 < NV) ? lp[lane + 32] : -1e30f;
    float v2 = (lane + 64 < NV) ? lp[lane + 64] : -1e30f;
    float m = fmaxf(v0, fmaxf(v1, v2));
    #pragma unroll
    for (int off = 16; off; off >>= 1) m = fmaxf(m, __shfl_xor_sync(0xffffffffu, m, off));
    float su = expf(v0 - m);
    if (lane + 32 < NV) su += expf(v1 - m);
    if (lane + 64 < NV) su += expf(v2 - m);
    #pragma unroll
    for (int off = 16; off; off >>= 1) su += __shfl_xor_sync(0xffffffffu, su, off);
    __shared__ double sm[8];
    if (lane == 0) {
        float lt = lp[tgt[row]];
        sm[wrp] = -((double)lt - (double)m - (double)logf(su));
    }
    __syncthreads();
    if (threadIdx.x == 0) {
        double t = sm[0] + sm[1] + sm[2] + sm[3] + sm[4] + sm[5] + sm[6] + sm[7];
        g_losspart[blockIdx.x] = t;
    }
}

__global__ void finalize_loss_kernel(float* __restrict__ out) {
    int tid = threadIdx.x;
    double s = 0.0;
    for (int i = tid; i < NLOSSB; i += 256) s += g_losspart[i];
    #pragma unroll
    for (int off = 16; off; off >>= 1) s += __shfl_xor_sync(0xffffffffu, s, off);
    __shared__ double sm[8];
    if ((tid & 31) == 0) sm[tid >> 5] = s;
    __syncthreads();
    if (tid == 0) {
        double t = sm[0] + sm[1] + sm[2] + sm[3] + sm[4] + sm[5] + sm[6] + sm[7];
        out[0] = (float)(t / (double)MTOT);
    }
}

// ================= launch =================
extern "C" void kernel_launch(void* const* d_in, const int* in_sizes, int n_in,
                              void* d_out, int out_size) {
    const int*   idx  = (const int*)d_in[0];
    const int*   tgt  = (const int*)d_in[1];
    const float* tok  = (const float*)d_in[2];
    const float* pos  = (const float*)d_in[3];
    const float* Wq   = (const float*)d_in[4];
    const float* Wk   = (const float*)d_in[5];
    const float* Wv   = (const float*)d_in[6];
    const float* Wpr  = (const float*)d_in[7];
    const float* bpr  = (const float*)d_in[8];
    const float* ln1g = (const float*)d_in[9];
    const float* ln1b = (const float*)d_in[10];
    const float* ln2g = (const float*)d_in[11];
    const float* ln2b = (const float*)d_in[12];
    const float* W1   = (const float*)d_in[13];
    const float* b1   = (const float*)d_in[14];
    const float* W2   = (const float*)d_in[15];
    const float* b2   = (const float*)d_in[16];
    const float* lnfg = (const float*)d_in[17];
    const float* lnfb = (const float*)d_in[18];
    const float* Wlm  = (const float*)d_in[19];
    const float* blm  = (const float*)d_in[20];
    float* out = (float*)d_out;

    float *px, *plog;
    __half *ph16, *pqkv, *po16, *pm16;
    __half *wq, *wp, *w1, *w2;
    cudaGetSymbolAddress((void**)&px, g_x);
    cudaGetSymbolAddress((void**)&plog, g_logits);
    cudaGetSymbolAddress((void**)&ph16, g_h16);
    cudaGetSymbolAddress((void**)&pqkv, g_qkv16);
    cudaGetSymbolAddress((void**)&po16, g_o16);
    cudaGetSymbolAddress((void**)&pm16, g_m16);
    cudaGetSymbolAddress((void**)&wq, g_wqkv);
    cudaGetSymbolAddress((void**)&wp, g_wpr);
    cudaGetSymbolAddress((void**)&w1, g_w1);
    cudaGetSymbolAddress((void**)&w2, g_w2);

    cudaFuncSetAttribute(flash_kernel, cudaFuncAttributeMaxDynamicSharedMemorySize, AT_SMEM);
    cudaFuncSetAttribute((gemm_main<0, NE>), cudaFuncAttributeMaxDynamicSharedMemorySize, HM_SMEM);
    cudaFuncSetAttribute((gemm_main<1, NE>), cudaFuncAttributeMaxDynamicSharedMemorySize, HM_SMEM);
    cudaFuncSetAttribute((gemm_main<2, NE>), cudaFuncAttributeMaxDynamicSharedMemorySize, HM_SMEM);
    cudaFuncSetAttribute((gemm_main<1, FF>), cudaFuncAttributeMaxDynamicSharedMemorySize, HM_SMEM);

    prep_all_kernel<<<(int)((PREP_N3 + 255) / 256), 256>>>(Wq, Wk, Wv, Wpr, W1, W2,
                                                           wq, wp, w1, w2);

    embed_kernel<<<(MTOT * NE + 255) / 256, 256>>>(idx, tok, pos);

    for (int l = 0; l < NL; l++) {
        ln16_kernel<<<MTOT / 128, 512>>>(px, ln1g + l * NE, ln1b + l * NE, ph16);
        gemm_main<0, NE><<<dim3(MTOT / 128, NQKV / 128), 512, HM_SMEM>>>(
            ph16, wq + (size_t)l * NQKV * NE, nullptr, nullptr, nullptr, pqkv);
        flash_kernel<<<dim3(NB * NH, 2), 256, AT_SMEM>>>(pqkv, po16);
        gemm_main<1, NE><<<dim3(MTOT / 128, NE / 128), 512, HM_SMEM>>>(
            po16, wp + (size_t)l * NE * NE, bpr + l * NE, px, px, nullptr);
        ln16_kernel<<<MTOT / 128, 512>>>(px, ln2g + l * NE, ln2b + l * NE, ph16);
        gemm_main<2, NE><<<dim3(MTOT / 128, FF / 128), 512, HM_SMEM>>>(
            ph16, w1 + (size_t)l * FF * NE, b1 + l * FF, nullptr, nullptr, pm16);
        gemm_main<1, FF><<<dim3(MTOT / 128, NE / 128), 512, HM_SMEM>>>(
            pm16, w2 + (size_t)l * NE * FF, b2 + l * NE, px, px, nullptr);
    }

    const int NLOG = MTOT * NV;
    float* logits = (out_size >= NLOG) ? out : plog;
    gemm_lm_kernel<<<dim3(MTOT / 64, (NV + 63) / 64), 256>>>(px, lnfg, lnfb, Wlm, blm, logits);

    loss_kernel<<<NLOSSB, 256>>>(logits, tgt);
    if (out_size > NLOG)       finalize_loss_kernel<<<1, 256>>>(out + NLOG);
    else if (out_size >= 1 && out_size < NLOG) finalize_loss_kernel<<<1, 256>>>(out);
}